// round 4
// baseline (speedup 1.0000x reference)
#include <cuda_runtime.h>
#include <cstdint>

#define Bx   4
#define Sx   1024
#define Hx   8
#define Dx   64
#define HDx  512
#define EMBx 512
#define XLx  1024
#define Jx   2048
#define KKx  32

// ---------------- device scratch ----------------
__device__ float g_q[Bx * Hx * Sx * Dx];     // exact (knn reads it)
__device__ float g_k[Bx * Hx * Jx * Dx];     // tf32-rounded
__device__ float g_v[Bx * Hx * Jx * Dx];     // tf32-rounded
__device__ float g_loc[Bx * Hx * Sx * Dx];   // g * local attn out
__device__ float g_ext[Bx * Sx * HDx];       // (1-g) * knn out

// ---------------- helpers ----------------
__device__ __forceinline__ float tf32r(float x) {
    uint32_t u;
    asm("cvt.rna.tf32.f32 %0, %1;" : "=r"(u) : "f"(x));
    return __uint_as_float(u);
}
__device__ __forceinline__ float4 tf32r4(float4 f) {
    f.x = tf32r(f.x); f.y = tf32r(f.y); f.z = tf32r(f.z); f.w = tf32r(f.w);
    return f;
}
__device__ __forceinline__ void mma_tf32(float* c, const float* a, const float* b)
{
    asm volatile(
        "mma.sync.aligned.m16n8k8.row.col.f32.tf32.tf32.f32 "
        "{%0,%1,%2,%3},{%4,%5,%6,%7},{%8,%9},{%0,%1,%2,%3};\n"
        : "+f"(c[0]), "+f"(c[1]), "+f"(c[2]), "+f"(c[3])
        : "r"(__float_as_uint(a[0])), "r"(__float_as_uint(a[1])),
          "r"(__float_as_uint(a[2])), "r"(__float_as_uint(a[3])),
          "r"(__float_as_uint(b[0])), "r"(__float_as_uint(b[1])));
}
__device__ __forceinline__ uint32_t smem_u32(const void* p) {
    return (uint32_t)__cvta_generic_to_shared(p);
}
__device__ __forceinline__ void cp_async16(uint32_t dst, const void* src) {
    asm volatile("cp.async.cg.shared.global [%0], [%1], 16;" :: "r"(dst), "l"(src));
}
__device__ __forceinline__ void cp_commit() {
    asm volatile("cp.async.commit_group;");
}
template<int N>
__device__ __forceinline__ void cp_wait() {
    asm volatile("cp.async.wait_group %0;" :: "n"(N));
}

#define SC_LOG2E 0.18033688011112042f   // 0.125 * log2(e)

// ===========================================================================
// Fused QKV GEMM + xl copy.  1792 blocks = 7*256:
//   rem<3 : GEMM block, gid = grp*3+rem in [0,768)
//   rem>=3: xl copy block, cid = grp*4+rem-3 in [0,1024)
// GEMM: 128x64 tiles of C[4096, 1536]; nsec 0:Q(1xTF32) 1:K 2:V (3xTF32).
// Register-prefetch pipelined over 16 k-chunks of 32.
// ===========================================================================
__global__ __launch_bounds__(256) void qkv_gemm(
    const float* __restrict__ x,
    const float* __restrict__ Wq, const float* __restrict__ bq,
    const float* __restrict__ Wk, const float* __restrict__ bk,
    const float* __restrict__ Wv, const float* __restrict__ bv,
    const float* __restrict__ xlm,
    float* __restrict__ kvout)
{
    extern __shared__ float smg[];
    int rem = blockIdx.x % 7;
    int grp = blockIdx.x / 7;

    if (rem >= 3) {
        // ---- xl copy (tf32-rounded into g_k/g_v) ----
        int base = (grp * 4 + rem - 3) * 1024;
#pragma unroll
        for (int i = 0; i < 4; i++) {
            int idx = base + i * 256 + threadIdx.x;
            int n4 = idx & 127;
            int rest = idx >> 7;
            int c = rest & 1;  rest >>= 1;
            int j = rest & 1023;
            int b = rest >> 10;
            float4 f = tf32r4(((const float4*)xlm)[idx]);
            int n = n4 * 4;
            int h = n >> 6, d = n & 63;
            float* dst = (c ? g_v : g_k) + (((size_t)(b * Hx + h)) * Jx + j) * Dx + d;
            *(float4*)dst = f;
        }
        return;
    }

    float* Ab = smg;                     // [128][36]
    float* Bb = Ab + 128 * 36;           // [64][36]
    float* Al = Bb + 64 * 36;
    float* Bl = Al + 128 * 36;

    int gid = grp * 3 + rem;             // 0..767
    int bm   = gid & 31;
    int nbi  = gid >> 5;                 // 0..23
    int nsec = nbi >> 3;
    int m0 = bm * 128, n0 = (nbi & 7) * 64;
    bool s3 = (nsec != 0);

    const float* W    = (nsec == 0) ? Wq : (nsec == 1) ? Wk : Wv;
    const float* bias = (nsec == 0) ? bq : (nsec == 1) ? bk : bv;

    int tid = threadIdx.x;
    int wid = tid >> 5, lane = tid & 31;
    int wm = wid & 3, wn = wid >> 2;
    int g = lane >> 2, tig = lane & 3;

    float acc[2][4][4];
#pragma unroll
    for (int i = 0; i < 2; i++)
#pragma unroll
        for (int j = 0; j < 4; j++)
#pragma unroll
            for (int e = 0; e < 4; e++) acc[i][j][e] = 0.f;

    int a_row = tid >> 1;
    int a_c0  = (tid & 1) * 16;
    int b_row = tid >> 2;
    int b_c0  = (tid & 3) * 8;

    const float* Agp = x + (size_t)(m0 + a_row) * 512 + a_c0;
    const float* Wgp = W + (size_t)(n0 + b_row) * 512 + b_c0;

    float4 ra[4], rb[2];
#pragma unroll
    for (int i = 0; i < 4; i++) ra[i] = *(const float4*)(Agp + i * 4);
#pragma unroll
    for (int i = 0; i < 2; i++) rb[i] = *(const float4*)(Wgp + i * 4);

    for (int kc = 0; kc < 16; kc++) {
        // ---- store staged regs to smem (tf32 split) ----
#pragma unroll
        for (int i = 0; i < 4; i++) {
            float4 f = ra[i];
            float4 bg = tf32r4(f);
            *(float4*)&Ab[a_row * 36 + a_c0 + i * 4] = bg;
            if (s3) {
                float4 sl;
                sl.x = tf32r(f.x - bg.x); sl.y = tf32r(f.y - bg.y);
                sl.z = tf32r(f.z - bg.z); sl.w = tf32r(f.w - bg.w);
                *(float4*)&Al[a_row * 36 + a_c0 + i * 4] = sl;
            }
        }
#pragma unroll
        for (int i = 0; i < 2; i++) {
            float4 f = rb[i];
            float4 bg = tf32r4(f);
            *(float4*)&Bb[b_row * 36 + b_c0 + i * 4] = bg;
            if (s3) {
                float4 sl;
                sl.x = tf32r(f.x - bg.x); sl.y = tf32r(f.y - bg.y);
                sl.z = tf32r(f.z - bg.z); sl.w = tf32r(f.w - bg.w);
                *(float4*)&Bl[b_row * 36 + b_c0 + i * 4] = sl;
            }
        }
        __syncthreads();

        // ---- prefetch next chunk (overlaps MMA below) ----
        if (kc < 15) {
            int k0 = (kc + 1) * 32;
#pragma unroll
            for (int i = 0; i < 4; i++) ra[i] = *(const float4*)(Agp + k0 + i * 4);
#pragma unroll
            for (int i = 0; i < 2; i++) rb[i] = *(const float4*)(Wgp + k0 + i * 4);
        }

#pragma unroll
        for (int kk = 0; kk < 4; kk++) {
            int kb = kk * 8;
            float a[2][4], as[2][4];
#pragma unroll
            for (int mi = 0; mi < 2; mi++) {
                int base = wm * 32 + mi * 16;
                a[mi][0] = Ab[(base + g)     * 36 + kb + tig];
                a[mi][1] = Ab[(base + g + 8) * 36 + kb + tig];
                a[mi][2] = Ab[(base + g)     * 36 + kb + tig + 4];
                a[mi][3] = Ab[(base + g + 8) * 36 + kb + tig + 4];
                if (s3) {
                    as[mi][0] = Al[(base + g)     * 36 + kb + tig];
                    as[mi][1] = Al[(base + g + 8) * 36 + kb + tig];
                    as[mi][2] = Al[(base + g)     * 36 + kb + tig + 4];
                    as[mi][3] = Al[(base + g + 8) * 36 + kb + tig + 4];
                }
            }
            float b[4][2], bs[4][2];
#pragma unroll
            for (int ni = 0; ni < 4; ni++) {
                int nb = wn * 32 + ni * 8;
                b[ni][0] = Bb[(nb + g) * 36 + kb + tig];
                b[ni][1] = Bb[(nb + g) * 36 + kb + tig + 4];
                if (s3) {
                    bs[ni][0] = Bl[(nb + g) * 36 + kb + tig];
                    bs[ni][1] = Bl[(nb + g) * 36 + kb + tig + 4];
                }
            }
#pragma unroll
            for (int mi = 0; mi < 2; mi++)
#pragma unroll
                for (int ni = 0; ni < 4; ni++) {
                    mma_tf32(acc[mi][ni], a[mi], b[ni]);
                    if (s3) {
                        mma_tf32(acc[mi][ni], a[mi], bs[ni]);
                        mma_tf32(acc[mi][ni], as[mi], b[ni]);
                    }
                }
        }
        __syncthreads();
    }

#pragma unroll
    for (int mi = 0; mi < 2; mi++) {
#pragma unroll
        for (int ni = 0; ni < 4; ni++) {
#pragma unroll
            for (int e = 0; e < 4; e++) {
                int m = m0 + wm * 32 + mi * 16 + g + ((e >> 1) * 8);
                int n = n0 + wn * 32 + ni * 8 + tig * 2 + (e & 1);
                float c = acc[mi][ni][e] + bias[n];
                int b = m >> 10, s = m & 1023;
                int h = n >> 6, d = n & 63;
                if (nsec == 0) {
                    g_q[(((size_t)(b * Hx + h)) * Sx + s) * Dx + d] = c;
                } else if (nsec == 1) {
                    g_k[(((size_t)(b * Hx + h)) * Jx + XLx + s) * Dx + d] = tf32r(c);
                    kvout[(((size_t)(b * Sx + s)) * 2 + 0) * HDx + n] = c;
                } else {
                    g_v[(((size_t)(b * Hx + h)) * Jx + XLx + s) * Dx + d] = tf32r(c);
                    kvout[(((size_t)(b * Sx + s)) * 2 + 1) * HDx + n] = c;
                }
            }
        }
    }
}

// ===========================================================================
// Fused attention + kNN, interleaved 1:8. 4608 blocks = 512*9:
//   blockIdx%9==8 : attention block, aid = blockIdx/9  (bh = aid>>4, qt = aid&15)
//   else          : kNN block, kid = blockIdx - blockIdx/9 in [0,4096)
// Attention: 64-q tile, split-key (2 warp groups of 32 keys), cp.async
// double-buffered K/V tiles (pre-rounded tf32 in g_k/g_v).
// ===========================================================================
__global__ __launch_bounds__(256) void attn_knn(const float* __restrict__ rel,
                                                const float* __restrict__ gate,
                                                const float* __restrict__ knn)
{
    extern __shared__ float sm[];
    int tid = threadIdx.x;
    int wid = tid >> 5, lane = tid & 31;

    if (blockIdx.x % 9 != 8) {
        // ------------------- kNN part -------------------
        int kb2 = blockIdx.x - blockIdx.x / 9;   // 0..4095
        int b = kb2 >> 10, s = kb2 & 1023;
        int h = wid;
        float* qsh = sm + wid * 2176;            // [64]
        float* vsh = qsh + 64;                   // [32][66]

        const float* qp = g_q + (((size_t)(b * Hx + h)) * Sx + s) * Dx;
        qsh[lane]      = qp[lane];
        qsh[lane + 32] = qp[lane + 32];
        __syncwarp();

        const float* kp = knn + ((((size_t)(b * Sx + s)) * KKx + lane) * 2) * HDx
                              + h * 64;
        float sc = 0.f;
#pragma unroll
        for (int i = 0; i < 16; i++) {
            float4 kf = *(const float4*)(kp + i * 4);
            float4 qf = *(const float4*)&qsh[i * 4];
            sc = fmaf(qf.x, kf.x, sc);
            sc = fmaf(qf.y, kf.y, sc);
            sc = fmaf(qf.z, kf.z, sc);
            sc = fmaf(qf.w, kf.w, sc);
        }
        sc *= 0.125f;

        float mx = sc;
        mx = fmaxf(mx, __shfl_xor_sync(0xffffffffu, mx, 16));
        mx = fmaxf(mx, __shfl_xor_sync(0xffffffffu, mx, 8));
        mx = fmaxf(mx, __shfl_xor_sync(0xffffffffu, mx, 4));
        mx = fmaxf(mx, __shfl_xor_sync(0xffffffffu, mx, 2));
        mx = fmaxf(mx, __shfl_xor_sync(0xffffffffu, mx, 1));
        float p = __expf(sc - mx);
        float sum = p;
        sum += __shfl_xor_sync(0xffffffffu, sum, 16);
        sum += __shfl_xor_sync(0xffffffffu, sum, 8);
        sum += __shfl_xor_sync(0xffffffffu, sum, 4);
        sum += __shfl_xor_sync(0xffffffffu, sum, 2);
        sum += __shfl_xor_sync(0xffffffffu, sum, 1);
        p /= sum;

        const float* vp = kp + HDx;
#pragma unroll
        for (int i = 0; i < 16; i++) {
            float4 vf = *(const float4*)(vp + i * 4);
            vsh[lane * 66 + i * 4 + 0] = p * vf.x;
            vsh[lane * 66 + i * 4 + 1] = p * vf.y;
            vsh[lane * 66 + i * 4 + 2] = p * vf.z;
            vsh[lane * 66 + i * 4 + 3] = p * vf.w;
        }
        __syncwarp();

        float acc0 = 0.f, acc1 = 0.f;
#pragma unroll
        for (int kk = 0; kk < 32; kk++) {
            acc0 += vsh[kk * 66 + lane];
            acc1 += vsh[kk * 66 + lane + 32];
        }

        float gg = 1.f / (1.f + __expf(-gate[h]));
        float w = 1.f - gg;
        size_t mi = ((size_t)(b * Sx + s)) * HDx + h * 64;
        g_ext[mi + lane]      = w * acc0;
        g_ext[mi + lane + 32] = w * acc1;
        return;
    }

    // ------------------- attention part -------------------
    float* Qs = sm;                       // [64][68]
    float* Kb = sm + 4352;                // 2 x [64][68]
    float* Vb = sm + 3 * 4352;            // 2 x [64][68]
    float* Pw = sm + 5 * 4352 + wid * 576;// per-warp [16][36]

    int aid = blockIdx.x / 9;             // 0..511
    int bh = aid >> 4;
    int h = bh & 7;
    int qt = aid & 15;
    int i0 = qt * 64;
    int wm = wid & 3, wn = wid >> 2;
    int g = lane >> 2, tig = lane & 3;
    int r0 = wm * 16 + g, r1 = r0 + 8;
    int qi0 = i0 + r0, qi1 = i0 + r1;

    int ntiles = qt + 17;
    const float* kbase = g_k + ((size_t)bh) * Jx * Dx;
    const float* vbase = g_v + ((size_t)bh) * Jx * Dx;
    const float* relrow0 = rel + ((size_t)h * Sx + qi0) * Jx;
    const float* relrow1 = rel + ((size_t)h * Sx + qi1) * Jx;

    // prefetch tile 0 (cp.async), load Q (rounded) meanwhile
    {
        float* Kd = Kb;
        float* Vd = Vb;
#pragma unroll
        for (int i = 0; i < 4; i++) {
            int idx = tid + i * 256;
            int row = idx >> 4, c4 = idx & 15;
            cp_async16(smem_u32(&Kd[row * 68 + c4 * 4]), kbase + row * 64 + c4 * 4);
            cp_async16(smem_u32(&Vd[row * 68 + c4 * 4]), vbase + row * 64 + c4 * 4);
        }
        cp_commit();
    }
    const float* qbase = g_q + (((size_t)bh) * Sx + i0) * Dx;
    for (int idx = tid; idx < 1024; idx += 256) {
        int row = idx >> 4, c4 = idx & 15;
        *(float4*)&Qs[row * 68 + c4 * 4] =
            tf32r4(*(const float4*)(qbase + row * 64 + c4 * 4));
    }

    float o[8][4];
#pragma unroll
    for (int ni = 0; ni < 8; ni++)
#pragma unroll
        for (int e = 0; e < 4; e++) o[ni][e] = 0.f;
    float m0 = -1e30f, m1 = -1e30f, l0 = 0.f, l1 = 0.f;

    for (int t = 0; t < ntiles; t++) {
        int j0 = t * 64;
        bool more = (t + 1 < ntiles);
        if (more) {
            int jn = (t + 1) * 64;
            float* Kd = Kb + ((t + 1) & 1) * 4352;
            float* Vd = Vb + ((t + 1) & 1) * 4352;
#pragma unroll
            for (int i = 0; i < 4; i++) {
                int idx = tid + i * 256;
                int row = idx >> 4, c4 = idx & 15;
                cp_async16(smem_u32(&Kd[row * 68 + c4 * 4]),
                           kbase + (size_t)(jn + row) * 64 + c4 * 4);
                cp_async16(smem_u32(&Vd[row * 68 + c4 * 4]),
                           vbase + (size_t)(jn + row) * 64 + c4 * 4);
            }
            cp_commit();
            cp_wait<1>();
        } else {
            cp_wait<0>();
        }
        __syncthreads();

        float* Ks = Kb + (t & 1) * 4352;
        float* Vs = Vb + (t & 1) * 4352;

        // hoisted rel loads (overlap with QK MMA)
        float2 rp0[4], rp1[4];
#pragma unroll
        for (int ni = 0; ni < 4; ni++) {
            int kcol = wn * 32 + ni * 8 + tig * 2;
            rp0[ni] = *(const float2*)(relrow0 + j0 + kcol);
            rp1[ni] = *(const float2*)(relrow1 + j0 + kcol);
        }

        // ---- S = Q K^T over this warp's 32-key half ----
        float c[4][4];
#pragma unroll
        for (int ni = 0; ni < 4; ni++)
#pragma unroll
            for (int e = 0; e < 4; e++) c[ni][e] = 0.f;
#pragma unroll
        for (int kk = 0; kk < 8; kk++) {
            int kb = kk * 8;
            float a[4];
            a[0] = Qs[r0 * 68 + kb + tig];
            a[1] = Qs[r1 * 68 + kb + tig];
            a[2] = Qs[r0 * 68 + kb + tig + 4];
            a[3] = Qs[r1 * 68 + kb + tig + 4];
#pragma unroll
            for (int ni = 0; ni < 4; ni++) {
                int krow = wn * 32 + ni * 8 + g;
                float b[2];
                b[0] = Ks[krow * 68 + kb + tig];
                b[1] = Ks[krow * 68 + kb + tig + 4];
                mma_tf32(c[ni], a, b);
            }
        }

        // ---- rel_pos + scale (exp2 domain) + causal mask ----
#pragma unroll
        for (int ni = 0; ni < 4; ni++) {
            int kcol = wn * 32 + ni * 8 + tig * 2;
            int kj = j0 + kcol;
            c[ni][0] = (kj     <= qi0 + XLx) ? (c[ni][0] + rp0[ni].x) * SC_LOG2E : -1e30f;
            c[ni][1] = (kj + 1 <= qi0 + XLx) ? (c[ni][1] + rp0[ni].y) * SC_LOG2E : -1e30f;
            c[ni][2] = (kj     <= qi1 + XLx) ? (c[ni][2] + rp1[ni].x) * SC_LOG2E : -1e30f;
            c[ni][3] = (kj + 1 <= qi1 + XLx) ? (c[ni][3] + rp1[ni].y) * SC_LOG2E : -1e30f;
        }

        // ---- warp-private online softmax (base-2) ----
        float rm0 = -1e30f, rm1 = -1e30f;
#pragma unroll
        for (int ni = 0; ni < 4; ni++) {
            rm0 = fmaxf(rm0, fmaxf(c[ni][0], c[ni][1]));
            rm1 = fmaxf(rm1, fmaxf(c[ni][2], c[ni][3]));
        }
        rm0 = fmaxf(rm0, __shfl_xor_sync(0xffffffffu, rm0, 1));
        rm0 = fmaxf(rm0, __shfl_xor_sync(0xffffffffu, rm0, 2));
        rm1 = fmaxf(rm1, __shfl_xor_sync(0xffffffffu, rm1, 1));
        rm1 = fmaxf(rm1, __shfl_xor_sync(0xffffffffu, rm1, 2));
        float mn0 = fmaxf(m0, rm0), mn1 = fmaxf(m1, rm1);
        float al0 = exp2f(m0 - mn0), al1 = exp2f(m1 - mn1);
        float ls0 = 0.f, ls1 = 0.f;
#pragma unroll
        for (int ni = 0; ni < 4; ni++) {
            int kcol = ni * 8 + tig * 2;
            float p00 = tf32r(exp2f(c[ni][0] - mn0));
            float p01 = tf32r(exp2f(c[ni][1] - mn0));
            float p10 = tf32r(exp2f(c[ni][2] - mn1));
            float p11 = tf32r(exp2f(c[ni][3] - mn1));
            ls0 += p00 + p01; ls1 += p10 + p11;
            Pw[g * 36 + kcol]           = p00;
            Pw[g * 36 + kcol + 1]       = p01;
            Pw[(g + 8) * 36 + kcol]     = p10;
            Pw[(g + 8) * 36 + kcol + 1] = p11;
        }
        ls0 += __shfl_xor_sync(0xffffffffu, ls0, 1);
        ls0 += __shfl_xor_sync(0xffffffffu, ls0, 2);
        ls1 += __shfl_xor_sync(0xffffffffu, ls1, 1);
        ls1 += __shfl_xor_sync(0xffffffffu, ls1, 2);
        l0 = l0 * al0 + ls0;
        l1 = l1 * al1 + ls1;
        m0 = mn0; m1 = mn1;
#pragma unroll
        for (int ni = 0; ni < 8; ni++) {
            o[ni][0] *= al0; o[ni][1] *= al0;
            o[ni][2] *= al1; o[ni][3] *= al1;
        }
        __syncwarp();

        // ---- O += P V ----
#pragma unroll
        for (int kk = 0; kk < 4; kk++) {
            int kb = kk * 8;
            float a[4];
            a[0] = Pw[g * 36 + kb + tig];
            a[1] = Pw[(g + 8) * 36 + kb + tig];
            a[2] = Pw[g * 36 + kb + tig + 4];
            a[3] = Pw[(g + 8) * 36 + kb + tig + 4];
            int vrow = wn * 32 + kb + tig;
#pragma unroll
            for (int ni = 0; ni < 8; ni++) {
                float b[2];
                b[0] = Vs[vrow * 68 + ni * 8 + g];
                b[1] = Vs[(vrow + 4) * 68 + ni * 8 + g];
                mma_tf32(o[ni], a, b);
            }
        }
        __syncthreads();    // all reads of Ks/Vs done before next overwrite
    }

    // ---- merge the two key-halves (scratch in buf0 of Kb/Vb) ----
    if (wn == 1) {
        float* M = Kb + (wm * 16) * 68;
#pragma unroll
        for (int ni = 0; ni < 8; ni++) {
            int col = ni * 8 + tig * 2;
            M[g * 68 + col]           = o[ni][0];
            M[g * 68 + col + 1]       = o[ni][1];
            M[(g + 8) * 68 + col]     = o[ni][2];
            M[(g + 8) * 68 + col + 1] = o[ni][3];
        }
        if (tig == 0) {
            Vb[r0] = m0; Vb[r1] = m1;
            Vb[64 + r0] = l0; Vb[64 + r1] = l1;
        }
    }
    __syncthreads();
    if (wn == 0) {
        float gsig = 1.f / (1.f + __expf(-gate[h]));
        float m1p0 = Vb[r0], m1p1 = Vb[r1];
        float l1p0 = Vb[64 + r0], l1p1 = Vb[64 + r1];
        float mt0 = fmaxf(m0, m1p0), mt1 = fmaxf(m1, m1p1);
        float a00 = exp2f(m0 - mt0),   a01 = exp2f(m1p0 - mt0);
        float a10 = exp2f(m1 - mt1),   a11 = exp2f(m1p1 - mt1);
        float inv0 = gsig / (l0 * a00 + l1p0 * a01);
        float inv1 = gsig / (l1 * a10 + l1p1 * a11);
        float* M = Kb + (wm * 16) * 68;
#pragma unroll
        for (int ni = 0; ni < 8; ni++) {
            int col = ni * 8 + tig * 2;
            float2 s0, s1;
            s0.x = (o[ni][0] * a00 + M[g * 68 + col]           * a01) * inv0;
            s0.y = (o[ni][1] * a00 + M[g * 68 + col + 1]       * a01) * inv0;
            s1.x = (o[ni][2] * a10 + M[(g + 8) * 68 + col]     * a11) * inv1;
            s1.y = (o[ni][3] * a10 + M[(g + 8) * 68 + col + 1] * a11) * inv1;
            *(float2*)&g_loc[(((size_t)bh) * Sx + qi0) * Dx + col] = s0;
            *(float2*)&g_loc[(((size_t)bh) * Sx + qi1) * Dx + col] = s1;
        }
    }
}

// ===========================================================================
// Output projection: out[4096,512] = (g_loc + g_ext) @ Wo^T + bo  (3xTF32),
// register-prefetch pipelined.
// ===========================================================================
__global__ __launch_bounds__(256) void out_gemm(const float* __restrict__ W,
                                                const float* __restrict__ bias,
                                                float* __restrict__ dst)
{
    extern __shared__ float smg[];
    float* Ab = smg;
    float* Bb = Ab + 128 * 36;
    float* Al = Bb + 64 * 36;
    float* Bl = Al + 128 * 36;

    int tid = threadIdx.x;
    int wid = tid >> 5, lane = tid & 31;
    int wm = wid & 3, wn = wid >> 2;
    int g = lane >> 2, tig = lane & 3;
    int m0 = blockIdx.x * 128, n0 = blockIdx.y * 64;

    float acc[2][4][4];
#pragma unroll
    for (int i = 0; i < 2; i++)
#pragma unroll
        for (int j = 0; j < 4; j++)
#pragma unroll
            for (int e = 0; e < 4; e++) acc[i][j][e] = 0.f;

    int a_row = tid >> 1;
    int a_c0  = (tid & 1) * 16;
    int b_row = tid >> 2;
    int b_c0  = (tid & 3) * 8;

    int mrow = m0 + a_row;
    int ab = mrow >> 10, as_ = mrow & 1023;
    const float* extp = g_ext + (size_t)mrow * 512;
    const float* Wgp = W + (size_t)(n0 + b_row) * 512 + b_c0;

    float4 ra[4], rb[2];
#pragma unroll
    for (int i = 0; i < 4; i++) {
        int cc = a_c0 + i * 4;
        int hh = cc >> 6, dd = cc & 63;
        float4 f1 = *(const float4*)&g_loc[(((size_t)(ab * Hx + hh)) * Sx + as_) * Dx + dd];
        float4 f2 = *(const float4*)(extp + cc);
        ra[i].x = f1.x + f2.x; ra[i].y = f1.y + f2.y;
        ra[i].z = f1.z + f2.z; ra[i].w = f1.w + f2.w;
    }
#pragma unroll
    for (int i = 0; i < 2; i++) rb[i] = *(const float4*)(Wgp + i * 4);

    for (int kc = 0; kc < 16; kc++) {
#pragma unroll
        for (int i = 0; i < 4; i++) {
            float4 f = ra[i];
            float4 bg = tf32r4(f);
            *(float4*)&Ab[a_row * 36 + a_c0 + i * 4] = bg;
            float4 sl;
            sl.x = tf32r(f.x - bg.x); sl.y = tf32r(f.y - bg.y);
            sl.z = tf32r(f.z - bg.z); sl.w = tf32r(f.w - bg.w);
            *(float4*)&Al[a_row * 36 + a_c0 + i * 4] = sl;
        }
#pragma unroll
        for (int i = 0; i < 2; i++) {
            float4 f = rb[i];
            float4 bg = tf32r4(f);
            *(float4*)&Bb[b_row * 36 + b_c0 + i * 4] = bg;
            float4 sl;
            sl.x = tf32r(f.x - bg.x); sl.y = tf32r(f.y - bg.y);
            sl.z = tf32r(f.z - bg.z); sl.w = tf32r(f.w - bg.w);
            *(float4*)&Bl[b_row * 36 + b_c0 + i * 4] = sl;
        }
        __syncthreads();

        if (kc < 15) {
            int k0 = (kc + 1) * 32;
#pragma unroll
            for (int i = 0; i < 4; i++) {
                int cc = a_c0 + k0 + i * 4;
                int hh = cc >> 6, dd = cc & 63;
                float4 f1 = *(const float4*)&g_loc[(((size_t)(ab * Hx + hh)) * Sx + as_) * Dx + dd];
                float4 f2 = *(const float4*)(extp + cc);
                ra[i].x = f1.x + f2.x; ra[i].y = f1.y + f2.y;
                ra[i].z = f1.z + f2.z; ra[i].w = f1.w + f2.w;
            }
#pragma unroll
            for (int i = 0; i < 2; i++) rb[i] = *(const float4*)(Wgp + k0 + i * 4);
        }

#pragma unroll
        for (int kk = 0; kk < 4; kk++) {
            int kb = kk * 8;
            float a[2][4], asr[2][4];
#pragma unroll
            for (int mi = 0; mi < 2; mi++) {
                int base = wm * 32 + mi * 16;
                a[mi][0] = Ab[(base + g)     * 36 + kb + tig];
                a[mi][1] = Ab[(base + g + 8) * 36 + kb + tig];
                a[mi][2] = Ab[(base + g)     * 36 + kb + tig + 4];
                a[mi][3] = Ab[(base + g + 8) * 36 + kb + tig + 4];
                asr[mi][0] = Al[(base + g)     * 36 + kb + tig];
                asr[mi][1] = Al[(base + g + 8) * 36 + kb + tig];
                asr[mi][2] = Al[(base + g)     * 36 + kb + tig + 4];
                asr[mi][3] = Al[(base + g + 8) * 36 + kb + tig + 4];
            }
            float b[4][2], bs[4][2];
#pragma unroll
            for (int ni = 0; ni < 4; ni++) {
                int nb = wn * 32 + ni * 8;
                b[ni][0] = Bb[(nb + g) * 36 + kb + tig];
                b[ni][1] = Bb[(nb + g) * 36 + kb + tig + 4];
                bs[ni][0] = Bl[(nb + g) * 36 + kb + tig];
                bs[ni][1] = Bl[(nb + g) * 36 + kb + tig + 4];
            }
#pragma unroll
            for (int mi = 0; mi < 2; mi++)
#pragma unroll
                for (int ni = 0; ni < 4; ni++) {
                    mma_tf32(acc[mi][ni], a[mi], b[ni]);
                    mma_tf32(acc[mi][ni], a[mi], bs[ni]);
                    mma_tf32(acc[mi][ni], asr[mi], b[ni]);
                }
        }
        __syncthreads();
    }

#pragma unroll
    for (int mi = 0; mi < 2; mi++)
#pragma unroll
        for (int ni = 0; ni < 4; ni++)
#pragma unroll
            for (int e = 0; e < 4; e++) {
                int m = m0 + wm * 32 + mi * 16 + g + ((e >> 1) * 8);
                int n = n0 + wn * 32 + ni * 8 + tig * 2 + (e & 1);
                dst[(size_t)m * EMBx + n] = acc[mi][ni][e] + bias[n];
            }
}

// ---------------------------------------------------------------------------
extern "C" void kernel_launch(void* const* d_in, const int* in_sizes, int n_in,
                              void* d_out, int out_size)
{
    (void)in_sizes; (void)n_in; (void)out_size;
    const float* x    = (const float*)d_in[0];
    const float* rel  = (const float*)d_in[1];
    const float* xlm  = (const float*)d_in[2];
    const float* knn  = (const float*)d_in[3];
    const float* Wq   = (const float*)d_in[4];
    const float* bq   = (const float*)d_in[5];
    const float* Wk   = (const float*)d_in[6];
    const float* bk   = (const float*)d_in[7];
    const float* Wv   = (const float*)d_in[8];
    const float* bv   = (const float*)d_in[9];
    const float* Wo   = (const float*)d_in[10];
    const float* bo   = (const float*)d_in[11];
    const float* gate = (const float*)d_in[12];

    float* out   = (float*)d_out;
    float* kvout = out + (size_t)Bx * Sx * EMBx;

    const int gsm = 2 * (128 * 36 + 64 * 36) * (int)sizeof(float);   // 55,296
    cudaFuncSetAttribute(qkv_gemm,
                         cudaFuncAttributeMaxDynamicSharedMemorySize, gsm);
    qkv_gemm<<<1792, 256, gsm>>>(x, Wq, bq, Wk, bk, Wv, bv, xlm, kvout);

    const int asmem = (5 * 4352 + 8 * 576) * (int)sizeof(float);     // 105,472
    cudaFuncSetAttribute(attn_knn,
                         cudaFuncAttributeMaxDynamicSharedMemorySize, asmem);
    attn_knn<<<4608, 256, asmem>>>(rel, gate, knn);

    cudaFuncSetAttribute(out_gemm,
                         cudaFuncAttributeMaxDynamicSharedMemorySize, gsm);
    out_gemm<<<dim3(32, 8), 256, gsm>>>(Wo, bo, out);
}

// round 6
// speedup vs baseline: 1.1054x; 1.1054x over previous
#include <cuda_runtime.h>
#include <cstdint>

#define Bx   4
#define Sx   1024
#define Hx   8
#define Dx   64
#define HDx  512
#define EMBx 512
#define XLx  1024
#define Jx   2048
#define KKx  32

// ---------------- device scratch ----------------
__device__ float g_q[Bx * Hx * Sx * Dx];
__device__ float g_k[Bx * Hx * Jx * Dx];
__device__ float g_v[Bx * Hx * Jx * Dx];
__device__ float g_loc[Bx * Hx * Sx * Dx];   // g * local attn out
__device__ float g_ext[Bx * Sx * HDx];       // (1-g) * knn out

// ---------------- helpers ----------------
__device__ __forceinline__ float tf32r(float x) {
    uint32_t u;
    asm("cvt.rna.tf32.f32 %0, %1;" : "=r"(u) : "f"(x));
    return __uint_as_float(u);
}
__device__ __forceinline__ float4 tf32r4(float4 f) {
    f.x = tf32r(f.x); f.y = tf32r(f.y); f.z = tf32r(f.z); f.w = tf32r(f.w);
    return f;
}
__device__ __forceinline__ void mma_tf32(float* c, const float* a, const float* b)
{
    asm volatile(
        "mma.sync.aligned.m16n8k8.row.col.f32.tf32.tf32.f32 "
        "{%0,%1,%2,%3},{%4,%5,%6,%7},{%8,%9},{%0,%1,%2,%3};\n"
        : "+f"(c[0]), "+f"(c[1]), "+f"(c[2]), "+f"(c[3])
        : "r"(__float_as_uint(a[0])), "r"(__float_as_uint(a[1])),
          "r"(__float_as_uint(a[2])), "r"(__float_as_uint(a[3])),
          "r"(__float_as_uint(b[0])), "r"(__float_as_uint(b[1])));
}

// ===========================================================================
// Fused QKV projection GEMM (+ xl_memory copy blocks). (round-3 version)
// ===========================================================================
__global__ __launch_bounds__(256) void qkv_gemm(
    const float* __restrict__ x,
    const float* __restrict__ Wq, const float* __restrict__ bq,
    const float* __restrict__ Wk, const float* __restrict__ bk,
    const float* __restrict__ Wv, const float* __restrict__ bv,
    const float* __restrict__ xlm,
    float* __restrict__ kvout)
{
    extern __shared__ float smg[];

    if (blockIdx.x >= 768) {
        int base = (blockIdx.x - 768) * 1024;
#pragma unroll
        for (int i = 0; i < 4; i++) {
            int idx = base + i * 256 + threadIdx.x;
            int n4 = idx & 127;
            int rest = idx >> 7;
            int c = rest & 1;  rest >>= 1;
            int j = rest & 1023;
            int b = rest >> 10;
            float4 f = ((const float4*)xlm)[idx];
            int n = n4 * 4;
            int h = n >> 6, d = n & 63;
            float* dst = (c ? g_v : g_k) + (((size_t)(b * Hx + h)) * Jx + j) * Dx + d;
            *(float4*)dst = f;
        }
        return;
    }

    float* Ab = smg;
    float* Bb = Ab + 128 * 36;
    float* Al = Bb + 64 * 36;
    float* Bl = Al + 128 * 36;

    int bm   = blockIdx.x & 31;
    int nbi  = blockIdx.x >> 5;
    int nsec = nbi >> 3;
    int m0 = bm * 128, n0 = (nbi & 7) * 64;
    bool s3 = (nsec != 0);

    const float* W    = (nsec == 0) ? Wq : (nsec == 1) ? Wk : Wv;
    const float* bias = (nsec == 0) ? bq : (nsec == 1) ? bk : bv;

    int tid = threadIdx.x;
    int wid = tid >> 5, lane = tid & 31;
    int wm = wid & 3, wn = wid >> 2;
    int g = lane >> 2, tig = lane & 3;

    float acc[2][4][4];
#pragma unroll
    for (int i = 0; i < 2; i++)
#pragma unroll
        for (int j = 0; j < 4; j++)
#pragma unroll
            for (int e = 0; e < 4; e++) acc[i][j][e] = 0.f;

    int a_row = tid >> 1;
    int a_c0  = (tid & 1) * 16;
    int b_row = tid >> 2;
    int b_c0  = (tid & 3) * 8;

    const float* Agp = x + (size_t)(m0 + a_row) * 512 + a_c0;
    const float* Wgp = W + (size_t)(n0 + b_row) * 512 + b_c0;

    for (int kc = 0; kc < 16; kc++) {
        int k0 = kc * 32;
        float4 ra[4], rb[2];
#pragma unroll
        for (int i = 0; i < 4; i++) ra[i] = *(const float4*)(Agp + k0 + i * 4);
#pragma unroll
        for (int i = 0; i < 2; i++) rb[i] = *(const float4*)(Wgp + k0 + i * 4);
        __syncthreads();
#pragma unroll
        for (int i = 0; i < 4; i++) {
            float4 f = ra[i];
            float4 bg = tf32r4(f);
            *(float4*)&Ab[a_row * 36 + a_c0 + i * 4] = bg;
            if (s3) {
                float4 sl;
                sl.x = tf32r(f.x - bg.x); sl.y = tf32r(f.y - bg.y);
                sl.z = tf32r(f.z - bg.z); sl.w = tf32r(f.w - bg.w);
                *(float4*)&Al[a_row * 36 + a_c0 + i * 4] = sl;
            }
        }
#pragma unroll
        for (int i = 0; i < 2; i++) {
            float4 f = rb[i];
            float4 bg = tf32r4(f);
            *(float4*)&Bb[b_row * 36 + b_c0 + i * 4] = bg;
            if (s3) {
                float4 sl;
                sl.x = tf32r(f.x - bg.x); sl.y = tf32r(f.y - bg.y);
                sl.z = tf32r(f.z - bg.z); sl.w = tf32r(f.w - bg.w);
                *(float4*)&Bl[b_row * 36 + b_c0 + i * 4] = sl;
            }
        }
        __syncthreads();

#pragma unroll
        for (int kk = 0; kk < 4; kk++) {
            int kb = kk * 8;
            float a[2][4], as[2][4];
#pragma unroll
            for (int mi = 0; mi < 2; mi++) {
                int base = wm * 32 + mi * 16;
                a[mi][0] = Ab[(base + g)     * 36 + kb + tig];
                a[mi][1] = Ab[(base + g + 8) * 36 + kb + tig];
                a[mi][2] = Ab[(base + g)     * 36 + kb + tig + 4];
                a[mi][3] = Ab[(base + g + 8) * 36 + kb + tig + 4];
                if (s3) {
                    as[mi][0] = Al[(base + g)     * 36 + kb + tig];
                    as[mi][1] = Al[(base + g + 8) * 36 + kb + tig];
                    as[mi][2] = Al[(base + g)     * 36 + kb + tig + 4];
                    as[mi][3] = Al[(base + g + 8) * 36 + kb + tig + 4];
                }
            }
            float b[4][2], bs[4][2];
#pragma unroll
            for (int ni = 0; ni < 4; ni++) {
                int nb = wn * 32 + ni * 8;
                b[ni][0] = Bb[(nb + g) * 36 + kb + tig];
                b[ni][1] = Bb[(nb + g) * 36 + kb + tig + 4];
                if (s3) {
                    bs[ni][0] = Bl[(nb + g) * 36 + kb + tig];
                    bs[ni][1] = Bl[(nb + g) * 36 + kb + tig + 4];
                }
            }
#pragma unroll
            for (int mi = 0; mi < 2; mi++)
#pragma unroll
                for (int ni = 0; ni < 4; ni++) {
                    mma_tf32(acc[mi][ni], a[mi], b[ni]);
                    if (s3) {
                        mma_tf32(acc[mi][ni], a[mi], bs[ni]);
                        mma_tf32(acc[mi][ni], as[mi], b[ni]);
                    }
                }
        }
    }

#pragma unroll
    for (int mi = 0; mi < 2; mi++) {
#pragma unroll
        for (int ni = 0; ni < 4; ni++) {
#pragma unroll
            for (int e = 0; e < 4; e++) {
                int m = m0 + wm * 32 + mi * 16 + g + ((e >> 1) * 8);
                int n = n0 + wn * 32 + ni * 8 + tig * 2 + (e & 1);
                float c = acc[mi][ni][e] + bias[n];
                int b = m >> 10, s = m & 1023;
                int h = n >> 6, d = n & 63;
                if (nsec == 0) {
                    g_q[(((size_t)(b * Hx + h)) * Sx + s) * Dx + d] = c;
                } else if (nsec == 1) {
                    g_k[(((size_t)(b * Hx + h)) * Jx + XLx + s) * Dx + d] = c;
                    kvout[(((size_t)(b * Sx + s)) * 2 + 0) * HDx + n] = c;
                } else {
                    g_v[(((size_t)(b * Hx + h)) * Jx + XLx + s) * Dx + d] = c;
                    kvout[(((size_t)(b * Sx + s)) * 2 + 1) * HDx + n] = c;
                }
            }
        }
    }
}

// ===========================================================================
// Fused attention + kNN, interleaved 1:8. 4608 blocks = 512*9.
// kNN: one block per (b,s); 256 threads stream 2 x 64KB chunks (16 keys each)
// coalesced through smem; warp = head; online softmax across chunks.
// ===========================================================================
__global__ __launch_bounds__(256) void attn_knn(const float* __restrict__ rel,
                                                const float* __restrict__ gate,
                                                const float* __restrict__ knn)
{
    extern __shared__ float sm[];
    int tid = threadIdx.x;
    int wid = tid >> 5, lane = tid & 31;

    if (blockIdx.x % 9 != 8) {
        // ------------------- kNN part (coalesced) -------------------
        int kid = blockIdx.x - blockIdx.x / 9;   // 0..4095
        int b = kid >> 10, s = kid & 1023;
        int h = wid;

        const float* qp = g_q + (((size_t)(b * Hx + h)) * Sx + s) * Dx;
        float2 qv = *(const float2*)(qp + lane * 2);

        const float4* src =
            (const float4*)(knn + ((size_t)(b * Sx + s)) * (KKx * 2 * HDx));
        float4* dstv = (float4*)sm;              // 16 keys x 1024 floats = 4096 float4

        float m = -1e30f, l = 0.f, a0 = 0.f, a1 = 0.f;

#pragma unroll
        for (int c = 0; c < 2; c++) {
            __syncthreads();
#pragma unroll
            for (int i = 0; i < 16; i++) {       // 16 float4/thread = 64KB total
                int idx = tid + i * 256;
                dstv[idx] = src[c * 4096 + idx];
            }
            __syncthreads();

            // 16 scores, warp-reduced dot products
            float sc[16];
#pragma unroll
            for (int kk = 0; kk < 16; kk++) {
                float2 kf = *(const float2*)(sm + kk * 1024 + h * 64 + lane * 2);
                float p = qv.x * kf.x + qv.y * kf.y;
                p += __shfl_xor_sync(0xffffffffu, p, 16);
                p += __shfl_xor_sync(0xffffffffu, p, 8);
                p += __shfl_xor_sync(0xffffffffu, p, 4);
                p += __shfl_xor_sync(0xffffffffu, p, 2);
                p += __shfl_xor_sync(0xffffffffu, p, 1);
                sc[kk] = p * 0.125f;
            }
            float cm = sc[0];
#pragma unroll
            for (int kk = 1; kk < 16; kk++) cm = fmaxf(cm, sc[kk]);
            float mn = fmaxf(m, cm);
            float al = __expf(m - mn);
            a0 *= al; a1 *= al; l *= al;
#pragma unroll
            for (int kk = 0; kk < 16; kk++) {
                float p = __expf(sc[kk] - mn);
                l += p;
                float2 vf = *(const float2*)(sm + kk * 1024 + 512 + h * 64 + lane * 2);
                a0 = fmaf(p, vf.x, a0);
                a1 = fmaf(p, vf.y, a1);
            }
            m = mn;
        }

        float gg = 1.f / (1.f + __expf(-gate[h]));
        float w = (1.f - gg) / l;
        float2 st; st.x = w * a0; st.y = w * a1;
        *(float2*)&g_ext[((size_t)(b * Sx + s)) * HDx + h * 64 + lane * 2] = st;
        return;
    }

    // ------------------- attention part (round-3) -------------------
    float* Qs = sm;                       // [64][68]
    float* Ks = Qs + 64 * 68;             // [64][68]
    float* Vs = Ks + 64 * 68;             // [64][68]
    float* Pw = Vs + 64 * 68 + wid * 576; // per-warp [16][36]

    int aid = blockIdx.x / 9;             // 0..511
    int bh = aid >> 4;
    int h = bh & 7;
    int qt = aid & 15;
    int i0 = qt * 64;
    int wm = wid & 3, wn = wid >> 2;
    int g = lane >> 2, tig = lane & 3;
    int r0 = wm * 16 + g, r1 = r0 + 8;
    int qi0 = i0 + r0, qi1 = i0 + r1;

    const float* qbase = g_q + (((size_t)bh) * Sx + i0) * Dx;
    for (int idx = tid; idx < 1024; idx += 256) {
        int row = idx >> 4, c4 = idx & 15;
        *(float4*)&Qs[row * 68 + c4 * 4] =
            tf32r4(*(const float4*)(qbase + row * 64 + c4 * 4));
    }

    float o[8][4];
#pragma unroll
    for (int ni = 0; ni < 8; ni++)
#pragma unroll
        for (int e = 0; e < 4; e++) o[ni][e] = 0.f;
    float m0 = -1e30f, m1 = -1e30f, l0 = 0.f, l1 = 0.f;

    int ntiles = qt + 17;
    const float* kbase = g_k + ((size_t)bh) * Jx * Dx;
    const float* vbase = g_v + ((size_t)bh) * Jx * Dx;
    const float* relrow0 = rel + ((size_t)h * Sx + qi0) * Jx;
    const float* relrow1 = rel + ((size_t)h * Sx + qi1) * Jx;

    for (int t = 0; t < ntiles; t++) {
        int j0 = t * 64;
        __syncthreads();
        for (int idx = tid; idx < 1024; idx += 256) {
            int row = idx >> 4, c4 = idx & 15;
            *(float4*)&Ks[row * 68 + c4 * 4] =
                tf32r4(*(const float4*)(kbase + (size_t)(j0 + row) * 64 + c4 * 4));
            *(float4*)&Vs[row * 68 + c4 * 4] =
                tf32r4(*(const float4*)(vbase + (size_t)(j0 + row) * 64 + c4 * 4));
        }
        __syncthreads();

        float c[4][4];
#pragma unroll
        for (int ni = 0; ni < 4; ni++)
#pragma unroll
            for (int e = 0; e < 4; e++) c[ni][e] = 0.f;
#pragma unroll
        for (int kk = 0; kk < 8; kk++) {
            int kb = kk * 8;
            float a[4];
            a[0] = Qs[r0 * 68 + kb + tig];
            a[1] = Qs[r1 * 68 + kb + tig];
            a[2] = Qs[r0 * 68 + kb + tig + 4];
            a[3] = Qs[r1 * 68 + kb + tig + 4];
#pragma unroll
            for (int ni = 0; ni < 4; ni++) {
                int krow = wn * 32 + ni * 8 + g;
                float b[2];
                b[0] = Ks[krow * 68 + kb + tig];
                b[1] = Ks[krow * 68 + kb + tig + 4];
                mma_tf32(c[ni], a, b);
            }
        }

#pragma unroll
        for (int ni = 0; ni < 4; ni++) {
            int kcol = wn * 32 + ni * 8 + tig * 2;
            int kj = j0 + kcol;
            float2 rp0 = *(const float2*)(relrow0 + kj);
            float2 rp1 = *(const float2*)(relrow1 + kj);
            c[ni][0] = (kj     <= qi0 + XLx) ? (c[ni][0] + rp0.x) * 0.125f : -1e30f;
            c[ni][1] = (kj + 1 <= qi0 + XLx) ? (c[ni][1] + rp0.y) * 0.125f : -1e30f;
            c[ni][2] = (kj     <= qi1 + XLx) ? (c[ni][2] + rp1.x) * 0.125f : -1e30f;
            c[ni][3] = (kj + 1 <= qi1 + XLx) ? (c[ni][3] + rp1.y) * 0.125f : -1e30f;
        }

        float rm0 = -1e30f, rm1 = -1e30f;
#pragma unroll
        for (int ni = 0; ni < 4; ni++) {
            rm0 = fmaxf(rm0, fmaxf(c[ni][0], c[ni][1]));
            rm1 = fmaxf(rm1, fmaxf(c[ni][2], c[ni][3]));
        }
        rm0 = fmaxf(rm0, __shfl_xor_sync(0xffffffffu, rm0, 1));
        rm0 = fmaxf(rm0, __shfl_xor_sync(0xffffffffu, rm0, 2));
        rm1 = fmaxf(rm1, __shfl_xor_sync(0xffffffffu, rm1, 1));
        rm1 = fmaxf(rm1, __shfl_xor_sync(0xffffffffu, rm1, 2));
        float mn0 = fmaxf(m0, rm0), mn1 = fmaxf(m1, rm1);
        float al0 = __expf(m0 - mn0), al1 = __expf(m1 - mn1);
        float ls0 = 0.f, ls1 = 0.f;
#pragma unroll
        for (int ni = 0; ni < 4; ni++) {
            int kcol = ni * 8 + tig * 2;
            float p00 = tf32r(__expf(c[ni][0] - mn0));
            float p01 = tf32r(__expf(c[ni][1] - mn0));
            float p10 = tf32r(__expf(c[ni][2] - mn1));
            float p11 = tf32r(__expf(c[ni][3] - mn1));
            ls0 += p00 + p01; ls1 += p10 + p11;
            Pw[g * 36 + kcol]           = p00;
            Pw[g * 36 + kcol + 1]       = p01;
            Pw[(g + 8) * 36 + kcol]     = p10;
            Pw[(g + 8) * 36 + kcol + 1] = p11;
        }
        ls0 += __shfl_xor_sync(0xffffffffu, ls0, 1);
        ls0 += __shfl_xor_sync(0xffffffffu, ls0, 2);
        ls1 += __shfl_xor_sync(0xffffffffu, ls1, 1);
        ls1 += __shfl_xor_sync(0xffffffffu, ls1, 2);
        l0 = l0 * al0 + ls0;
        l1 = l1 * al1 + ls1;
        m0 = mn0; m1 = mn1;
#pragma unroll
        for (int ni = 0; ni < 8; ni++) {
            o[ni][0] *= al0; o[ni][1] *= al0;
            o[ni][2] *= al1; o[ni][3] *= al1;
        }
        __syncwarp();

#pragma unroll
        for (int kk = 0; kk < 4; kk++) {
            int kb = kk * 8;
            float a[4];
            a[0] = Pw[g * 36 + kb + tig];
            a[1] = Pw[(g + 8) * 36 + kb + tig];
            a[2] = Pw[g * 36 + kb + tig + 4];
            a[3] = Pw[(g + 8) * 36 + kb + tig + 4];
            int vrow = wn * 32 + kb + tig;
#pragma unroll
            for (int ni = 0; ni < 8; ni++) {
                float b[2];
                b[0] = Vs[vrow * 68 + ni * 8 + g];
                b[1] = Vs[(vrow + 4) * 68 + ni * 8 + g];
                mma_tf32(o[ni], a, b);
            }
        }
    }

    __syncthreads();
    if (wn == 1) {
        float* M = Ks + (wm * 16) * 68;
#pragma unroll
        for (int ni = 0; ni < 8; ni++) {
            int col = ni * 8 + tig * 2;
            M[g * 68 + col]           = o[ni][0];
            M[g * 68 + col + 1]       = o[ni][1];
            M[(g + 8) * 68 + col]     = o[ni][2];
            M[(g + 8) * 68 + col + 1] = o[ni][3];
        }
        if (tig == 0) {
            Vs[r0] = m0; Vs[r1] = m1;
            Vs[64 + r0] = l0; Vs[64 + r1] = l1;
        }
    }
    __syncthreads();
    if (wn == 0) {
        float gsig = 1.f / (1.f + __expf(-gate[h]));
        float m1p0 = Vs[r0], m1p1 = Vs[r1];
        float l1p0 = Vs[64 + r0], l1p1 = Vs[64 + r1];
        float mt0 = fmaxf(m0, m1p0), mt1 = fmaxf(m1, m1p1);
        float a00 = __expf(m0 - mt0),   a01 = __expf(m1p0 - mt0);
        float a10 = __expf(m1 - mt1),   a11 = __expf(m1p1 - mt1);
        float inv0 = gsig / (l0 * a00 + l1p0 * a01);
        float inv1 = gsig / (l1 * a10 + l1p1 * a11);
        float* M = Ks + (wm * 16) * 68;
#pragma unroll
        for (int ni = 0; ni < 8; ni++) {
            int col = ni * 8 + tig * 2;
            float2 s0, s1;
            s0.x = (o[ni][0] * a00 + M[g * 68 + col]           * a01) * inv0;
            s0.y = (o[ni][1] * a00 + M[g * 68 + col + 1]       * a01) * inv0;
            s1.x = (o[ni][2] * a10 + M[(g + 8) * 68 + col]     * a11) * inv1;
            s1.y = (o[ni][3] * a10 + M[(g + 8) * 68 + col + 1] * a11) * inv1;
            *(float2*)&g_loc[(((size_t)bh) * Sx + qi0) * Dx + col] = s0;
            *(float2*)&g_loc[(((size_t)bh) * Sx + qi1) * Dx + col] = s1;
        }
    }
}

// ===========================================================================
// Output projection: out[4096,512] = (g_loc + g_ext) @ Wo^T + bo (round-3)
// ===========================================================================
__global__ __launch_bounds__(256) void out_gemm(const float* __restrict__ W,
                                                const float* __restrict__ bias,
                                                float* __restrict__ dst)
{
    extern __shared__ float smg[];
    float* Ab = smg;
    float* Bb = Ab + 128 * 36;
    float* Al = Bb + 64 * 36;
    float* Bl = Al + 128 * 36;

    int tid = threadIdx.x;
    int wid = tid >> 5, lane = tid & 31;
    int wm = wid & 3, wn = wid >> 2;
    int g = lane >> 2, tig = lane & 3;
    int m0 = blockIdx.x * 128, n0 = blockIdx.y * 64;

    float acc[2][4][4];
#pragma unroll
    for (int i = 0; i < 2; i++)
#pragma unroll
        for (int j = 0; j < 4; j++)
#pragma unroll
            for (int e = 0; e < 4; e++) acc[i][j][e] = 0.f;

    int a_row = tid >> 1;
    int a_c0  = (tid & 1) * 16;
    int b_row = tid >> 2;
    int b_c0  = (tid & 3) * 8;

    int mrow = m0 + a_row;
    int ab = mrow >> 10, as_ = mrow & 1023;
    const float* extp = g_ext + (size_t)mrow * 512;
    const float* Wgp = W + (size_t)(n0 + b_row) * 512 + b_c0;

    for (int kc = 0; kc < 16; kc++) {
        int k0 = kc * 32;
        float4 ra[4], rb[2];
#pragma unroll
        for (int i = 0; i < 4; i++) {
            int cc = a_c0 + k0 + i * 4;
            int hh = cc >> 6, dd = cc & 63;
            float4 f1 = *(const float4*)&g_loc[(((size_t)(ab * Hx + hh)) * Sx + as_) * Dx + dd];
            float4 f2 = *(const float4*)(extp + cc);
            ra[i].x = f1.x + f2.x; ra[i].y = f1.y + f2.y;
            ra[i].z = f1.z + f2.z; ra[i].w = f1.w + f2.w;
        }
#pragma unroll
        for (int i = 0; i < 2; i++) rb[i] = *(const float4*)(Wgp + k0 + i * 4);
        __syncthreads();
#pragma unroll
        for (int i = 0; i < 4; i++) {
            float4 f = ra[i];
            float4 bg = tf32r4(f);
            *(float4*)&Ab[a_row * 36 + a_c0 + i * 4] = bg;
            float4 sl;
            sl.x = tf32r(f.x - bg.x); sl.y = tf32r(f.y - bg.y);
            sl.z = tf32r(f.z - bg.z); sl.w = tf32r(f.w - bg.w);
            *(float4*)&Al[a_row * 36 + a_c0 + i * 4] = sl;
        }
#pragma unroll
        for (int i = 0; i < 2; i++) {
            float4 f = rb[i];
            float4 bg = tf32r4(f);
            *(float4*)&Bb[b_row * 36 + b_c0 + i * 4] = bg;
            float4 sl;
            sl.x = tf32r(f.x - bg.x); sl.y = tf32r(f.y - bg.y);
            sl.z = tf32r(f.z - bg.z); sl.w = tf32r(f.w - bg.w);
            *(float4*)&Bl[b_row * 36 + b_c0 + i * 4] = sl;
        }
        __syncthreads();

#pragma unroll
        for (int kk = 0; kk < 4; kk++) {
            int kb = kk * 8;
            float a[2][4], asr[2][4];
#pragma unroll
            for (int mi = 0; mi < 2; mi++) {
                int base = wm * 32 + mi * 16;
                a[mi][0] = Ab[(base + g)     * 36 + kb + tig];
                a[mi][1] = Ab[(base + g + 8) * 36 + kb + tig];
                a[mi][2] = Ab[(base + g)     * 36 + kb + tig + 4];
                a[mi][3] = Ab[(base + g + 8) * 36 + kb + tig + 4];
                asr[mi][0] = Al[(base + g)     * 36 + kb + tig];
                asr[mi][1] = Al[(base + g + 8) * 36 + kb + tig];
                asr[mi][2] = Al[(base + g)     * 36 + kb + tig + 4];
                asr[mi][3] = Al[(base + g + 8) * 36 + kb + tig + 4];
            }
            float b[4][2], bs[4][2];
#pragma unroll
            for (int ni = 0; ni < 4; ni++) {
                int nb = wn * 32 + ni * 8;
                b[ni][0] = Bb[(nb + g) * 36 + kb + tig];
                b[ni][1] = Bb[(nb + g) * 36 + kb + tig + 4];
                bs[ni][0] = Bl[(nb + g) * 36 + kb + tig];
                bs[ni][1] = Bl[(nb + g) * 36 + kb + tig + 4];
            }
#pragma unroll
            for (int mi = 0; mi < 2; mi++)
#pragma unroll
                for (int ni = 0; ni < 4; ni++) {
                    mma_tf32(acc[mi][ni], a[mi], b[ni]);
                    mma_tf32(acc[mi][ni], a[mi], bs[ni]);
                    mma_tf32(acc[mi][ni], asr[mi], b[ni]);
                }
        }
    }

#pragma unroll
    for (int mi = 0; mi < 2; mi++)
#pragma unroll
        for (int ni = 0; ni < 4; ni++)
#pragma unroll
            for (int e = 0; e < 4; e++) {
                int m = m0 + wm * 32 + mi * 16 + g + ((e >> 1) * 8);
                int n = n0 + wn * 32 + ni * 8 + tig * 2 + (e & 1);
                dst[(size_t)m * EMBx + n] = acc[mi][ni][e] + bias[n];
            }
}

// ---------------------------------------------------------------------------
extern "C" void kernel_launch(void* const* d_in, const int* in_sizes, int n_in,
                              void* d_out, int out_size)
{
    (void)in_sizes; (void)n_in; (void)out_size;
    const float* x    = (const float*)d_in[0];
    const float* rel  = (const float*)d_in[1];
    const float* xlm  = (const float*)d_in[2];
    const float* knn  = (const float*)d_in[3];
    const float* Wq   = (const float*)d_in[4];
    const float* bq   = (const float*)d_in[5];
    const float* Wk   = (const float*)d_in[6];
    const float* bk   = (const float*)d_in[7];
    const float* Wv   = (const float*)d_in[8];
    const float* bv   = (const float*)d_in[9];
    const float* Wo   = (const float*)d_in[10];
    const float* bo   = (const float*)d_in[11];
    const float* gate = (const float*)d_in[12];

    float* out   = (float*)d_out;
    float* kvout = out + (size_t)Bx * Sx * EMBx;

    const int gsm = 2 * (128 * 36 + 64 * 36) * (int)sizeof(float);   // 55,296
    cudaFuncSetAttribute(qkv_gemm,
                         cudaFuncAttributeMaxDynamicSharedMemorySize, gsm);
    qkv_gemm<<<1792, 256, gsm>>>(x, Wq, bq, Wk, bk, Wv, bv, xlm, kvout);

    const int asmem = (3 * 64 * 68 + 8 * 576) * (int)sizeof(float);  // 70,656
    cudaFuncSetAttribute(attn_knn,
                         cudaFuncAttributeMaxDynamicSharedMemorySize, asmem);
    attn_knn<<<4608, 256, asmem>>>(rel, gate, knn);

    cudaFuncSetAttribute(out_gemm,
                         cudaFuncAttributeMaxDynamicSharedMemorySize, gsm);
    out_gemm<<<dim3(32, 8), 256, gsm>>>(Wo, bo, out);
}

// round 7
// speedup vs baseline: 1.1307x; 1.0228x over previous
#include <cuda_runtime.h>
#include <cstdint>

#define Bx   4
#define Sx   1024
#define Hx   8
#define Dx   64
#define HDx  512
#define EMBx 512
#define XLx  1024
#define Jx   2048
#define KKx  32

// ---------------- device scratch ----------------
__device__ float g_q[Bx * Hx * Sx * Dx];     // exact (knn reads it)
__device__ float g_k[Bx * Hx * Jx * Dx];     // tf32-rounded at producer
__device__ float g_v[Bx * Hx * Jx * Dx];     // tf32-rounded at producer
__device__ float g_loc[Bx * Hx * Sx * Dx];   // g * local attn out
__device__ float g_ext[Bx * Sx * HDx];       // (1-g) * knn out

// ---------------- helpers ----------------
__device__ __forceinline__ float tf32r(float x) {
    uint32_t u;
    asm("cvt.rna.tf32.f32 %0, %1;" : "=r"(u) : "f"(x));
    return __uint_as_float(u);
}
__device__ __forceinline__ float4 tf32r4(float4 f) {
    f.x = tf32r(f.x); f.y = tf32r(f.y); f.z = tf32r(f.z); f.w = tf32r(f.w);
    return f;
}
__device__ __forceinline__ void mma_tf32(float* c, const float* a, const float* b)
{
    asm volatile(
        "mma.sync.aligned.m16n8k8.row.col.f32.tf32.tf32.f32 "
        "{%0,%1,%2,%3},{%4,%5,%6,%7},{%8,%9},{%0,%1,%2,%3};\n"
        : "+f"(c[0]), "+f"(c[1]), "+f"(c[2]), "+f"(c[3])
        : "r"(__float_as_uint(a[0])), "r"(__float_as_uint(a[1])),
          "r"(__float_as_uint(a[2])), "r"(__float_as_uint(a[3])),
          "r"(__float_as_uint(b[0])), "r"(__float_as_uint(b[1])));
}

// ===========================================================================
// Fused QKV projection GEMM (+ xl_memory copy blocks).
// Epilogue now writes tf32-rounded K/V into g_k/g_v (kvout stays exact).
// ===========================================================================
__global__ __launch_bounds__(256) void qkv_gemm(
    const float* __restrict__ x,
    const float* __restrict__ Wq, const float* __restrict__ bq,
    const float* __restrict__ Wk, const float* __restrict__ bk,
    const float* __restrict__ Wv, const float* __restrict__ bv,
    const float* __restrict__ xlm,
    float* __restrict__ kvout)
{
    extern __shared__ float smg[];

    if (blockIdx.x >= 768) {
        int base = (blockIdx.x - 768) * 1024;
#pragma unroll
        for (int i = 0; i < 4; i++) {
            int idx = base + i * 256 + threadIdx.x;
            int n4 = idx & 127;
            int rest = idx >> 7;
            int c = rest & 1;  rest >>= 1;
            int j = rest & 1023;
            int b = rest >> 10;
            float4 f = tf32r4(((const float4*)xlm)[idx]);
            int n = n4 * 4;
            int h = n >> 6, d = n & 63;
            float* dst = (c ? g_v : g_k) + (((size_t)(b * Hx + h)) * Jx + j) * Dx + d;
            *(float4*)dst = f;
        }
        return;
    }

    float* Ab = smg;
    float* Bb = Ab + 128 * 36;
    float* Al = Bb + 64 * 36;
    float* Bl = Al + 128 * 36;

    int bm   = blockIdx.x & 31;
    int nbi  = blockIdx.x >> 5;
    int nsec = nbi >> 3;
    int m0 = bm * 128, n0 = (nbi & 7) * 64;
    bool s3 = (nsec != 0);

    const float* W    = (nsec == 0) ? Wq : (nsec == 1) ? Wk : Wv;
    const float* bias = (nsec == 0) ? bq : (nsec == 1) ? bk : bv;

    int tid = threadIdx.x;
    int wid = tid >> 5, lane = tid & 31;
    int wm = wid & 3, wn = wid >> 2;
    int g = lane >> 2, tig = lane & 3;

    float acc[2][4][4];
#pragma unroll
    for (int i = 0; i < 2; i++)
#pragma unroll
        for (int j = 0; j < 4; j++)
#pragma unroll
            for (int e = 0; e < 4; e++) acc[i][j][e] = 0.f;

    int a_row = tid >> 1;
    int a_c0  = (tid & 1) * 16;
    int b_row = tid >> 2;
    int b_c0  = (tid & 3) * 8;

    const float* Agp = x + (size_t)(m0 + a_row) * 512 + a_c0;
    const float* Wgp = W + (size_t)(n0 + b_row) * 512 + b_c0;

    for (int kc = 0; kc < 16; kc++) {
        int k0 = kc * 32;
        float4 ra[4], rb[2];
#pragma unroll
        for (int i = 0; i < 4; i++) ra[i] = *(const float4*)(Agp + k0 + i * 4);
#pragma unroll
        for (int i = 0; i < 2; i++) rb[i] = *(const float4*)(Wgp + k0 + i * 4);
        __syncthreads();
#pragma unroll
        for (int i = 0; i < 4; i++) {
            float4 f = ra[i];
            float4 bg = tf32r4(f);
            *(float4*)&Ab[a_row * 36 + a_c0 + i * 4] = bg;
            if (s3) {
                float4 sl;
                sl.x = tf32r(f.x - bg.x); sl.y = tf32r(f.y - bg.y);
                sl.z = tf32r(f.z - bg.z); sl.w = tf32r(f.w - bg.w);
                *(float4*)&Al[a_row * 36 + a_c0 + i * 4] = sl;
            }
        }
#pragma unroll
        for (int i = 0; i < 2; i++) {
            float4 f = rb[i];
            float4 bg = tf32r4(f);
            *(float4*)&Bb[b_row * 36 + b_c0 + i * 4] = bg;
            if (s3) {
                float4 sl;
                sl.x = tf32r(f.x - bg.x); sl.y = tf32r(f.y - bg.y);
                sl.z = tf32r(f.z - bg.z); sl.w = tf32r(f.w - bg.w);
                *(float4*)&Bl[b_row * 36 + b_c0 + i * 4] = sl;
            }
        }
        __syncthreads();

#pragma unroll
        for (int kk = 0; kk < 4; kk++) {
            int kb = kk * 8;
            float a[2][4], as[2][4];
#pragma unroll
            for (int mi = 0; mi < 2; mi++) {
                int base = wm * 32 + mi * 16;
                a[mi][0] = Ab[(base + g)     * 36 + kb + tig];
                a[mi][1] = Ab[(base + g + 8) * 36 + kb + tig];
                a[mi][2] = Ab[(base + g)     * 36 + kb + tig + 4];
                a[mi][3] = Ab[(base + g + 8) * 36 + kb + tig + 4];
                if (s3) {
                    as[mi][0] = Al[(base + g)     * 36 + kb + tig];
                    as[mi][1] = Al[(base + g + 8) * 36 + kb + tig];
                    as[mi][2] = Al[(base + g)     * 36 + kb + tig + 4];
                    as[mi][3] = Al[(base + g + 8) * 36 + kb + tig + 4];
                }
            }
            float b[4][2], bs[4][2];
#pragma unroll
            for (int ni = 0; ni < 4; ni++) {
                int nb = wn * 32 + ni * 8;
                b[ni][0] = Bb[(nb + g) * 36 + kb + tig];
                b[ni][1] = Bb[(nb + g) * 36 + kb + tig + 4];
                if (s3) {
                    bs[ni][0] = Bl[(nb + g) * 36 + kb + tig];
                    bs[ni][1] = Bl[(nb + g) * 36 + kb + tig + 4];
                }
            }
#pragma unroll
            for (int mi = 0; mi < 2; mi++)
#pragma unroll
                for (int ni = 0; ni < 4; ni++) {
                    mma_tf32(acc[mi][ni], a[mi], b[ni]);
                    if (s3) {
                        mma_tf32(acc[mi][ni], a[mi], bs[ni]);
                        mma_tf32(acc[mi][ni], as[mi], b[ni]);
                    }
                }
        }
    }

#pragma unroll
    for (int mi = 0; mi < 2; mi++) {
#pragma unroll
        for (int ni = 0; ni < 4; ni++) {
#pragma unroll
            for (int e = 0; e < 4; e++) {
                int m = m0 + wm * 32 + mi * 16 + g + ((e >> 1) * 8);
                int n = n0 + wn * 32 + ni * 8 + tig * 2 + (e & 1);
                float c = acc[mi][ni][e] + bias[n];
                int b = m >> 10, s = m & 1023;
                int h = n >> 6, d = n & 63;
                if (nsec == 0) {
                    g_q[(((size_t)(b * Hx + h)) * Sx + s) * Dx + d] = c;
                } else if (nsec == 1) {
                    g_k[(((size_t)(b * Hx + h)) * Jx + XLx + s) * Dx + d] = tf32r(c);
                    kvout[(((size_t)(b * Sx + s)) * 2 + 0) * HDx + n] = c;
                } else {
                    g_v[(((size_t)(b * Hx + h)) * Jx + XLx + s) * Dx + d] = tf32r(c);
                    kvout[(((size_t)(b * Sx + s)) * 2 + 1) * HDx + n] = c;
                }
            }
        }
    }
}

// ===========================================================================
// Fused attention + kNN, interleaved 1:8. 4608 blocks = 512*9.
// Attention tile loads are now plain float4 copies (K/V pre-rounded).
// ===========================================================================
__global__ __launch_bounds__(256) void attn_knn(const float* __restrict__ rel,
                                                const float* __restrict__ gate,
                                                const float* __restrict__ knn)
{
    extern __shared__ float sm[];
    int tid = threadIdx.x;
    int wid = tid >> 5, lane = tid & 31;

    if (blockIdx.x % 9 != 8) {
        // ------------------- kNN part (coalesced) -------------------
        int kid = blockIdx.x - blockIdx.x / 9;   // 0..4095
        int b = kid >> 10, s = kid & 1023;
        int h = wid;

        const float* qp = g_q + (((size_t)(b * Hx + h)) * Sx + s) * Dx;
        float2 qv = *(const float2*)(qp + lane * 2);

        const float4* src =
            (const float4*)(knn + ((size_t)(b * Sx + s)) * (KKx * 2 * HDx));
        float4* dstv = (float4*)sm;              // 4096 float4 = 64KB

        float m = -1e30f, l = 0.f, a0 = 0.f, a1 = 0.f;

#pragma unroll
        for (int c = 0; c < 2; c++) {
            __syncthreads();
#pragma unroll
            for (int i = 0; i < 16; i++) {
                int idx = tid + i * 256;
                dstv[idx] = src[c * 4096 + idx];
            }
            __syncthreads();

            float sc[16];
#pragma unroll
            for (int kk = 0; kk < 16; kk++) {
                float2 kf = *(const float2*)(sm + kk * 1024 + h * 64 + lane * 2);
                float p = qv.x * kf.x + qv.y * kf.y;
                p += __shfl_xor_sync(0xffffffffu, p, 16);
                p += __shfl_xor_sync(0xffffffffu, p, 8);
                p += __shfl_xor_sync(0xffffffffu, p, 4);
                p += __shfl_xor_sync(0xffffffffu, p, 2);
                p += __shfl_xor_sync(0xffffffffu, p, 1);
                sc[kk] = p * 0.125f;
            }
            float cm = sc[0];
#pragma unroll
            for (int kk = 1; kk < 16; kk++) cm = fmaxf(cm, sc[kk]);
            float mn = fmaxf(m, cm);
            float al = __expf(m - mn);
            a0 *= al; a1 *= al; l *= al;
#pragma unroll
            for (int kk = 0; kk < 16; kk++) {
                float p = __expf(sc[kk] - mn);
                l += p;
                float2 vf = *(const float2*)(sm + kk * 1024 + 512 + h * 64 + lane * 2);
                a0 = fmaf(p, vf.x, a0);
                a1 = fmaf(p, vf.y, a1);
            }
            m = mn;
        }

        float gg = 1.f / (1.f + __expf(-gate[h]));
        float w = (1.f - gg) / l;
        float2 st; st.x = w * a0; st.y = w * a1;
        *(float2*)&g_ext[((size_t)(b * Sx + s)) * HDx + h * 64 + lane * 2] = st;
        return;
    }

    // ------------------- attention part -------------------
    float* Qs = sm;                       // [64][68]
    float* Ks = Qs + 64 * 68;             // [64][68]
    float* Vs = Ks + 64 * 68;             // [64][68]
    float* Pw = Vs + 64 * 68 + wid * 576; // per-warp [16][36]

    int aid = blockIdx.x / 9;             // 0..511
    int bh = aid >> 4;
    int h = bh & 7;
    int qt = aid & 15;
    int i0 = qt * 64;
    int wm = wid & 3, wn = wid >> 2;
    int g = lane >> 2, tig = lane & 3;
    int r0 = wm * 16 + g, r1 = r0 + 8;
    int qi0 = i0 + r0, qi1 = i0 + r1;

    const float* qbase = g_q + (((size_t)bh) * Sx + i0) * Dx;
    for (int idx = tid; idx < 1024; idx += 256) {
        int row = idx >> 4, c4 = idx & 15;
        *(float4*)&Qs[row * 68 + c4 * 4] =
            tf32r4(*(const float4*)(qbase + row * 64 + c4 * 4));
    }

    float o[8][4];
#pragma unroll
    for (int ni = 0; ni < 8; ni++)
#pragma unroll
        for (int e = 0; e < 4; e++) o[ni][e] = 0.f;
    float m0 = -1e30f, m1 = -1e30f, l0 = 0.f, l1 = 0.f;

    int ntiles = qt + 17;
    const float* kbase = g_k + ((size_t)bh) * Jx * Dx;
    const float* vbase = g_v + ((size_t)bh) * Jx * Dx;
    const float* relrow0 = rel + ((size_t)h * Sx + qi0) * Jx;
    const float* relrow1 = rel + ((size_t)h * Sx + qi1) * Jx;

    for (int t = 0; t < ntiles; t++) {
        int j0 = t * 64;
        __syncthreads();
        for (int idx = tid; idx < 1024; idx += 256) {
            int row = idx >> 4, c4 = idx & 15;
            *(float4*)&Ks[row * 68 + c4 * 4] =
                *(const float4*)(kbase + (size_t)(j0 + row) * 64 + c4 * 4);
            *(float4*)&Vs[row * 68 + c4 * 4] =
                *(const float4*)(vbase + (size_t)(j0 + row) * 64 + c4 * 4);
        }
        __syncthreads();

        float c[4][4];
#pragma unroll
        for (int ni = 0; ni < 4; ni++)
#pragma unroll
            for (int e = 0; e < 4; e++) c[ni][e] = 0.f;
#pragma unroll
        for (int kk = 0; kk < 8; kk++) {
            int kb = kk * 8;
            float a[4];
            a[0] = Qs[r0 * 68 + kb + tig];
            a[1] = Qs[r1 * 68 + kb + tig];
            a[2] = Qs[r0 * 68 + kb + tig + 4];
            a[3] = Qs[r1 * 68 + kb + tig + 4];
#pragma unroll
            for (int ni = 0; ni < 4; ni++) {
                int krow = wn * 32 + ni * 8 + g;
                float b[2];
                b[0] = Ks[krow * 68 + kb + tig];
                b[1] = Ks[krow * 68 + kb + tig + 4];
                mma_tf32(c[ni], a, b);
            }
        }

#pragma unroll
        for (int ni = 0; ni < 4; ni++) {
            int kcol = wn * 32 + ni * 8 + tig * 2;
            int kj = j0 + kcol;
            float2 rp0 = *(const float2*)(relrow0 + kj);
            float2 rp1 = *(const float2*)(relrow1 + kj);
            c[ni][0] = (kj     <= qi0 + XLx) ? (c[ni][0] + rp0.x) * 0.125f : -1e30f;
            c[ni][1] = (kj + 1 <= qi0 + XLx) ? (c[ni][1] + rp0.y) * 0.125f : -1e30f;
            c[ni][2] = (kj     <= qi1 + XLx) ? (c[ni][2] + rp1.x) * 0.125f : -1e30f;
            c[ni][3] = (kj + 1 <= qi1 + XLx) ? (c[ni][3] + rp1.y) * 0.125f : -1e30f;
        }

        float rm0 = -1e30f, rm1 = -1e30f;
#pragma unroll
        for (int ni = 0; ni < 4; ni++) {
            rm0 = fmaxf(rm0, fmaxf(c[ni][0], c[ni][1]));
            rm1 = fmaxf(rm1, fmaxf(c[ni][2], c[ni][3]));
        }
        rm0 = fmaxf(rm0, __shfl_xor_sync(0xffffffffu, rm0, 1));
        rm0 = fmaxf(rm0, __shfl_xor_sync(0xffffffffu, rm0, 2));
        rm1 = fmaxf(rm1, __shfl_xor_sync(0xffffffffu, rm1, 1));
        rm1 = fmaxf(rm1, __shfl_xor_sync(0xffffffffu, rm1, 2));
        float mn0 = fmaxf(m0, rm0), mn1 = fmaxf(m1, rm1);
        float al0 = __expf(m0 - mn0), al1 = __expf(m1 - mn1);
        float ls0 = 0.f, ls1 = 0.f;
#pragma unroll
        for (int ni = 0; ni < 4; ni++) {
            int kcol = ni * 8 + tig * 2;
            float p00 = tf32r(__expf(c[ni][0] - mn0));
            float p01 = tf32r(__expf(c[ni][1] - mn0));
            float p10 = tf32r(__expf(c[ni][2] - mn1));
            float p11 = tf32r(__expf(c[ni][3] - mn1));
            ls0 += p00 + p01; ls1 += p10 + p11;
            Pw[g * 36 + kcol]           = p00;
            Pw[g * 36 + kcol + 1]       = p01;
            Pw[(g + 8) * 36 + kcol]     = p10;
            Pw[(g + 8) * 36 + kcol + 1] = p11;
        }
        ls0 += __shfl_xor_sync(0xffffffffu, ls0, 1);
        ls0 += __shfl_xor_sync(0xffffffffu, ls0, 2);
        ls1 += __shfl_xor_sync(0xffffffffu, ls1, 1);
        ls1 += __shfl_xor_sync(0xffffffffu, ls1, 2);
        l0 = l0 * al0 + ls0;
        l1 = l1 * al1 + ls1;
        m0 = mn0; m1 = mn1;
#pragma unroll
        for (int ni = 0; ni < 8; ni++) {
            o[ni][0] *= al0; o[ni][1] *= al0;
            o[ni][2] *= al1; o[ni][3] *= al1;
        }
        __syncwarp();

#pragma unroll
        for (int kk = 0; kk < 4; kk++) {
            int kb = kk * 8;
            float a[4];
            a[0] = Pw[g * 36 + kb + tig];
            a[1] = Pw[(g + 8) * 36 + kb + tig];
            a[2] = Pw[g * 36 + kb + tig + 4];
            a[3] = Pw[(g + 8) * 36 + kb + tig + 4];
            int vrow = wn * 32 + kb + tig;
#pragma unroll
            for (int ni = 0; ni < 8; ni++) {
                float b[2];
                b[0] = Vs[vrow * 68 + ni * 8 + g];
                b[1] = Vs[(vrow + 4) * 68 + ni * 8 + g];
                mma_tf32(o[ni], a, b);
            }
        }
    }

    __syncthreads();
    if (wn == 1) {
        float* M = Ks + (wm * 16) * 68;
#pragma unroll
        for (int ni = 0; ni < 8; ni++) {
            int col = ni * 8 + tig * 2;
            M[g * 68 + col]           = o[ni][0];
            M[g * 68 + col + 1]       = o[ni][1];
            M[(g + 8) * 68 + col]     = o[ni][2];
            M[(g + 8) * 68 + col + 1] = o[ni][3];
        }
        if (tig == 0) {
            Vs[r0] = m0; Vs[r1] = m1;
            Vs[64 + r0] = l0; Vs[64 + r1] = l1;
        }
    }
    __syncthreads();
    if (wn == 0) {
        float gsig = 1.f / (1.f + __expf(-gate[h]));
        float m1p0 = Vs[r0], m1p1 = Vs[r1];
        float l1p0 = Vs[64 + r0], l1p1 = Vs[64 + r1];
        float mt0 = fmaxf(m0, m1p0), mt1 = fmaxf(m1, m1p1);
        float a00 = __expf(m0 - mt0),   a01 = __expf(m1p0 - mt0);
        float a10 = __expf(m1 - mt1),   a11 = __expf(m1p1 - mt1);
        float inv0 = gsig / (l0 * a00 + l1p0 * a01);
        float inv1 = gsig / (l1 * a10 + l1p1 * a11);
        float* M = Ks + (wm * 16) * 68;
#pragma unroll
        for (int ni = 0; ni < 8; ni++) {
            int col = ni * 8 + tig * 2;
            float2 s0, s1;
            s0.x = (o[ni][0] * a00 + M[g * 68 + col]           * a01) * inv0;
            s0.y = (o[ni][1] * a00 + M[g * 68 + col + 1]       * a01) * inv0;
            s1.x = (o[ni][2] * a10 + M[(g + 8) * 68 + col]     * a11) * inv1;
            s1.y = (o[ni][3] * a10 + M[(g + 8) * 68 + col + 1] * a11) * inv1;
            *(float2*)&g_loc[(((size_t)bh) * Sx + qi0) * Dx + col] = s0;
            *(float2*)&g_loc[(((size_t)bh) * Sx + qi1) * Dx + col] = s1;
        }
    }
}

// ===========================================================================
// Output projection: out[4096,512] = (g_loc + g_ext) @ Wo^T + bo (3xTF32)
// ===========================================================================
__global__ __launch_bounds__(256) void out_gemm(const float* __restrict__ W,
                                                const float* __restrict__ bias,
                                                float* __restrict__ dst)
{
    extern __shared__ float smg[];
    float* Ab = smg;
    float* Bb = Ab + 128 * 36;
    float* Al = Bb + 64 * 36;
    float* Bl = Al + 128 * 36;

    int tid = threadIdx.x;
    int wid = tid >> 5, lane = tid & 31;
    int wm = wid & 3, wn = wid >> 2;
    int g = lane >> 2, tig = lane & 3;
    int m0 = blockIdx.x * 128, n0 = blockIdx.y * 64;

    float acc[2][4][4];
#pragma unroll
    for (int i = 0; i < 2; i++)
#pragma unroll
        for (int j = 0; j < 4; j++)
#pragma unroll
            for (int e = 0; e < 4; e++) acc[i][j][e] = 0.f;

    int a_row = tid >> 1;
    int a_c0  = (tid & 1) * 16;
    int b_row = tid >> 2;
    int b_c0  = (tid & 3) * 8;

    int mrow = m0 + a_row;
    int ab = mrow >> 10, as_ = mrow & 1023;
    const float* extp = g_ext + (size_t)mrow * 512;
    const float* Wgp = W + (size_t)(n0 + b_row) * 512 + b_c0;

    for (int kc = 0; kc < 16; kc++) {
        int k0 = kc * 32;
        float4 ra[4], rb[2];
#pragma unroll
        for (int i = 0; i < 4; i++) {
            int cc = a_c0 + k0 + i * 4;
            int hh = cc >> 6, dd = cc & 63;
            float4 f1 = *(const float4*)&g_loc[(((size_t)(ab * Hx + hh)) * Sx + as_) * Dx + dd];
            float4 f2 = *(const float4*)(extp + cc);
            ra[i].x = f1.x + f2.x; ra[i].y = f1.y + f2.y;
            ra[i].z = f1.z + f2.z; ra[i].w = f1.w + f2.w;
        }
#pragma unroll
        for (int i = 0; i < 2; i++) rb[i] = *(const float4*)(Wgp + k0 + i * 4);
        __syncthreads();
#pragma unroll
        for (int i = 0; i < 4; i++) {
            float4 f = ra[i];
            float4 bg = tf32r4(f);
            *(float4*)&Ab[a_row * 36 + a_c0 + i * 4] = bg;
            float4 sl;
            sl.x = tf32r(f.x - bg.x); sl.y = tf32r(f.y - bg.y);
            sl.z = tf32r(f.z - bg.z); sl.w = tf32r(f.w - bg.w);
            *(float4*)&Al[a_row * 36 + a_c0 + i * 4] = sl;
        }
#pragma unroll
        for (int i = 0; i < 2; i++) {
            float4 f = rb[i];
            float4 bg = tf32r4(f);
            *(float4*)&Bb[b_row * 36 + b_c0 + i * 4] = bg;
            float4 sl;
            sl.x = tf32r(f.x - bg.x); sl.y = tf32r(f.y - bg.y);
            sl.z = tf32r(f.z - bg.z); sl.w = tf32r(f.w - bg.w);
            *(float4*)&Bl[b_row * 36 + b_c0 + i * 4] = sl;
        }
        __syncthreads();

#pragma unroll
        for (int kk = 0; kk < 4; kk++) {
            int kb = kk * 8;
            float a[2][4], asr[2][4];
#pragma unroll
            for (int mi = 0; mi < 2; mi++) {
                int base = wm * 32 + mi * 16;
                a[mi][0] = Ab[(base + g)     * 36 + kb + tig];
                a[mi][1] = Ab[(base + g + 8) * 36 + kb + tig];
                a[mi][2] = Ab[(base + g)     * 36 + kb + tig + 4];
                a[mi][3] = Ab[(base + g + 8) * 36 + kb + tig + 4];
                asr[mi][0] = Al[(base + g)     * 36 + kb + tig];
                asr[mi][1] = Al[(base + g + 8) * 36 + kb + tig];
                asr[mi][2] = Al[(base + g)     * 36 + kb + tig + 4];
                asr[mi][3] = Al[(base + g + 8) * 36 + kb + tig + 4];
            }
            float b[4][2], bs[4][2];
#pragma unroll
            for (int ni = 0; ni < 4; ni++) {
                int nb = wn * 32 + ni * 8;
                b[ni][0] = Bb[(nb + g) * 36 + kb + tig];
                b[ni][1] = Bb[(nb + g) * 36 + kb + tig + 4];
                bs[ni][0] = Bl[(nb + g) * 36 + kb + tig];
                bs[ni][1] = Bl[(nb + g) * 36 + kb + tig + 4];
            }
#pragma unroll
            for (int mi = 0; mi < 2; mi++)
#pragma unroll
                for (int ni = 0; ni < 4; ni++) {
                    mma_tf32(acc[mi][ni], a[mi], b[ni]);
                    mma_tf32(acc[mi][ni], a[mi], bs[ni]);
                    mma_tf32(acc[mi][ni], asr[mi], b[ni]);
                }
        }
    }

#pragma unroll
    for (int mi = 0; mi < 2; mi++)
#pragma unroll
        for (int ni = 0; ni < 4; ni++)
#pragma unroll
            for (int e = 0; e < 4; e++) {
                int m = m0 + wm * 32 + mi * 16 + g + ((e >> 1) * 8);
                int n = n0 + wn * 32 + ni * 8 + tig * 2 + (e & 1);
                dst[(size_t)m * EMBx + n] = acc[mi][ni][e] + bias[n];
            }
}

// ---------------------------------------------------------------------------
extern "C" void kernel_launch(void* const* d_in, const int* in_sizes, int n_in,
                              void* d_out, int out_size)
{
    (void)in_sizes; (void)n_in; (void)out_size;
    const float* x    = (const float*)d_in[0];
    const float* rel  = (const float*)d_in[1];
    const float* xlm  = (const float*)d_in[2];
    const float* knn  = (const float*)d_in[3];
    const float* Wq   = (const float*)d_in[4];
    const float* bq   = (const float*)d_in[5];
    const float* Wk   = (const float*)d_in[6];
    const float* bk   = (const float*)d_in[7];
    const float* Wv   = (const float*)d_in[8];
    const float* bv   = (const float*)d_in[9];
    const float* Wo   = (const float*)d_in[10];
    const float* bo   = (const float*)d_in[11];
    const float* gate = (const float*)d_in[12];

    float* out   = (float*)d_out;
    float* kvout = out + (size_t)Bx * Sx * EMBx;

    const int gsm = 2 * (128 * 36 + 64 * 36) * (int)sizeof(float);   // 55,296
    cudaFuncSetAttribute(qkv_gemm,
                         cudaFuncAttributeMaxDynamicSharedMemorySize, gsm);
    qkv_gemm<<<1792, 256, gsm>>>(x, Wq, bq, Wk, bk, Wv, bv, xlm, kvout);

    const int asmem = (3 * 64 * 68 + 8 * 576) * (int)sizeof(float);  // 70,656
    cudaFuncSetAttribute(attn_knn,
                         cudaFuncAttributeMaxDynamicSharedMemorySize, asmem);
    attn_knn<<<4608, 256, asmem>>>(rel, gate, knn);

    cudaFuncSetAttribute(out_gemm,
                         cudaFuncAttributeMaxDynamicSharedMemorySize, gsm);
    out_gemm<<<dim3(32, 8), 256, gsm>>>(Wo, bo, out);
}